// round 1
// baseline (speedup 1.0000x reference)
#include <cuda_runtime.h>

#define DIM 256
#define PLANE (DIM*DIM)
#define NELEM (DIM*DIM*DIM)

// Block layout: blockDim = (64, 4, 1) = 256 threads.
//   threadIdx.x (0..63): w-chunk of 4 elements at w0 = 4*tx (float4 aligned)
//   threadIdx.y (0..3):  h row within block
// Grid: (1, 64, 254): h = 1 + 4*by + ty (masked to <=254), d = 1 + bz.
#define GRID_Y 64
#define GRID_Z (DIM-2)
#define NBLOCKS (GRID_Y*GRID_Z)   // 16256

__device__ float g_partials[NBLOCKS];

__device__ __forceinline__ float4 mag4(const float* __restrict__ x, int base, int w0) {
    const float4 c  = *reinterpret_cast<const float4*>(x + base);
    const float4 up = *reinterpret_cast<const float4*>(x + base - DIM);
    const float4 dn = *reinterpret_cast<const float4*>(x + base + DIM);
    const float4 fr = *reinterpret_cast<const float4*>(x + base - PLANE);
    const float4 bk = *reinterpret_cast<const float4*>(x + base + PLANE);
    const float left  = (w0 > 0)       ? x[base - 1] : 0.0f;
    const float right = (w0 + 4 < DIM) ? x[base + 4] : 0.0f;

    // W-axis central diffs for the 4 elements
    const float gw0 = c.y   - left;
    const float gw1 = c.z   - c.x;
    const float gw2 = c.w   - c.y;
    const float gw3 = right - c.z;
    // H-axis and D-axis diffs
    const float gh0 = dn.x - up.x, gh1 = dn.y - up.y, gh2 = dn.z - up.z, gh3 = dn.w - up.w;
    const float gd0 = bk.x - fr.x, gd1 = bk.y - fr.y, gd2 = bk.z - fr.z, gd3 = bk.w - fr.w;

    float4 m;
    m.x = sqrtf(gw0*gw0 + gh0*gh0 + gd0*gd0 + 1e-6f);
    m.y = sqrtf(gw1*gw1 + gh1*gh1 + gd1*gd1 + 1e-6f);
    m.z = sqrtf(gw2*gw2 + gh2*gh2 + gd2*gd2 + 1e-6f);
    m.w = sqrtf(gw3*gw3 + gh3*gh3 + gd3*gd3 + 1e-6f);
    return m;
}

__global__ __launch_bounds__(256) void grad_loss_main(const float* __restrict__ x1,
                                                      const float* __restrict__ x2) {
    const int tx = threadIdx.x;               // 0..63
    const int ty = threadIdx.y;               // 0..3
    const int h  = 1 + (blockIdx.y * 4 + ty); // 1..256 (mask h<=254)
    const int d  = 1 + blockIdx.z;            // 1..254
    const int w0 = tx * 4;

    float local = 0.0f;
    if (h <= DIM - 2) {
        const int base = (d * DIM + h) * DIM + w0;
        const float4 m1 = mag4(x1, base, w0);
        const float4 m2 = mag4(x2, base, w0);

        // Edge-pad weights (pad-by-replication == weight 2 on first/last interior
        // index along each axis). Along w: w0 is a multiple of 4, so
        //   j=0 (w=w0):   interior only if tx>0, weight 1
        //   j=1 (w=w0+1): weight 2 iff tx==0 (w==1)
        //   j=2 (w=w0+2): weight 2 iff tx==63 (w==254)
        //   j=3 (w=w0+3): interior only if tx<63, weight 1
        const float wd  = (d == 1 || d == DIM - 2) ? 2.0f : 1.0f;
        const float wh  = (h == 1 || h == DIM - 2) ? 2.0f : 1.0f;
        const float whd = wd * wh;

        float s = 0.0f;
        if (tx > 0)  s += fabsf(m1.x - m2.x);
        s += ((tx == 0)  ? 2.0f : 1.0f) * fabsf(m1.y - m2.y);
        s += ((tx == 63) ? 2.0f : 1.0f) * fabsf(m1.z - m2.z);
        if (tx < 63) s += fabsf(m1.w - m2.w);
        local = whd * s;
    }

    // Block reduction: warp shfl, then 8 warp partials via smem.
    #pragma unroll
    for (int off = 16; off > 0; off >>= 1)
        local += __shfl_xor_sync(0xffffffffu, local, off);

    __shared__ float ssum[8];
    const int tid  = ty * 64 + tx;
    const int warp = tid >> 5;
    const int lane = tid & 31;
    if (lane == 0) ssum[warp] = local;
    __syncthreads();
    if (warp == 0) {
        float v = (lane < 8) ? ssum[lane] : 0.0f;
        #pragma unroll
        for (int off = 4; off > 0; off >>= 1)
            v += __shfl_xor_sync(0xffffffffu, v, off);
        if (lane == 0)
            g_partials[blockIdx.y + GRID_Y * blockIdx.z] = v;
    }
}

__global__ __launch_bounds__(1024) void grad_loss_final(float* __restrict__ out) {
    float s = 0.0f;
    for (int i = threadIdx.x; i < NBLOCKS; i += 1024)
        s += g_partials[i];
    #pragma unroll
    for (int off = 16; off > 0; off >>= 1)
        s += __shfl_xor_sync(0xffffffffu, s, off);

    __shared__ float ssum[32];
    const int warp = threadIdx.x >> 5;
    const int lane = threadIdx.x & 31;
    if (lane == 0) ssum[warp] = s;
    __syncthreads();
    if (warp == 0) {
        float v = ssum[lane];  // 32 warps exactly
        #pragma unroll
        for (int off = 16; off > 0; off >>= 1)
            v += __shfl_xor_sync(0xffffffffu, v, off);
        if (lane == 0)
            out[0] = v * (1.0f / (float)NELEM);
    }
}

extern "C" void kernel_launch(void* const* d_in, const int* in_sizes, int n_in,
                              void* d_out, int out_size) {
    const float* x1 = (const float*)d_in[0];
    const float* x2 = (const float*)d_in[1];
    float* out = (float*)d_out;
    (void)in_sizes; (void)n_in; (void)out_size;

    dim3 block(64, 4, 1);
    dim3 grid(1, GRID_Y, GRID_Z);
    grad_loss_main<<<grid, block>>>(x1, x2);
    grad_loss_final<<<1, 1024>>>(out);
}

// round 2
// speedup vs baseline: 1.1084x; 1.1084x over previous
#include <cuda_runtime.h>

#define DIM 256
#define PLANE (DIM*DIM)
#define NELEM (DIM*DIM*DIM)

#define HTILES 64          // h tiles of 4 rows
#define DCHUNKS 16         // d split for parallelism
#define DPC 16             // d-steps per chunk (15*16 + 14 = 254)
#define NBLOCKS (HTILES*DCHUNKS)   // 1024

__device__ float g_partials[NBLOCKS];
__device__ unsigned int g_count = 0;   // wraps to 0 each launch via atomicInc

__global__ __launch_bounds__(256) void grad_loss_fused(const float* __restrict__ x1,
                                                       const float* __restrict__ x2,
                                                       float* __restrict__ out) {
    // smem: plane d, rows h0-1 .. h0+4 (6 rows) for both inputs
    __shared__ float sm[2][6][DIM];
    __shared__ float ssum[8];
    __shared__ int s_last;

    const int tx = threadIdx.x;            // 0..63 -> w quad
    const int ty = threadIdx.y;            // 0..3  -> h row in tile
    const int htile = blockIdx.x;          // 0..63
    const int chunk = blockIdx.y;          // 0..15
    const int bid = chunk * HTILES + htile;

    const int h0 = 1 + htile * 4;
    const int h  = h0 + ty;                // 1..256
    const int w0 = tx * 4;
    const int d0 = 1 + chunk * DPC;
    const int d1 = min(DIM - 2, d0 + DPC - 1);

    const bool hload = (h < DIM);          // row exists (needed as neighbor too)
    const bool hcomp = (h <= DIM - 2);     // interior output row

    const int rowoff = h * DIM + w0;

    // d-window registers: A = plane d-1, B = plane d, C = plane d+1
    float4 A0, A1, B0, B1, C0, C1;
    if (hload) {
        A0 = *(const float4*)(x1 + (d0 - 1) * PLANE + rowoff);
        A1 = *(const float4*)(x2 + (d0 - 1) * PLANE + rowoff);
        B0 = *(const float4*)(x1 + d0 * PLANE + rowoff);
        B1 = *(const float4*)(x2 + d0 * PLANE + rowoff);
    } else {
        A0 = A1 = B0 = B1 = make_float4(0.f, 0.f, 0.f, 0.f);
    }

    // Boundary-row staging assignment: each thread stages one quad of one
    // boundary row:  ty>>1 selects input, ty&1 selects top(h0-1)/bottom(h0+4).
    const int bin   = ty >> 1;
    const int bbot  = ty & 1;
    const int brow  = bbot ? (h0 + 4) : (h0 - 1);
    const int bidx  = bbot ? 5 : 0;
    const bool bvalid = (brow < DIM);
    const float* bp = bin ? x2 : x1;

    const float wh = (h == 1 || h == DIM - 2) ? 2.0f : 1.0f;

    float local = 0.0f;

    for (int d = d0; d <= d1; ++d) {
        __syncthreads();   // protect smem from previous iteration's readers
        // stage plane d: center rows from B regs, boundary rows from gmem
        if (hload) {
            *(float4*)&sm[0][ty + 1][w0] = B0;
            *(float4*)&sm[1][ty + 1][w0] = B1;
        }
        if (bvalid) {
            *(float4*)&sm[bin][bidx][w0] =
                *(const float4*)(bp + d * PLANE + brow * DIM + w0);
        }
        // prefetch plane d+1 (d+1 <= 255 always)
        if (hload) {
            C0 = *(const float4*)(x1 + (d + 1) * PLANE + rowoff);
            C1 = *(const float4*)(x2 + (d + 1) * PLANE + rowoff);
        }
        __syncthreads();

        if (hcomp) {
            const float wd = (d == 1 || d == DIM - 2) ? 2.0f : 1.0f;

            // input 0
            float lf0 = (tx > 0)  ? sm[0][ty + 1][w0 - 1] : 0.0f;
            float rt0 = (tx < 63) ? sm[0][ty + 1][w0 + 4] : 0.0f;
            float4 up0 = *(float4*)&sm[0][ty][w0];
            float4 dn0 = *(float4*)&sm[0][ty + 2][w0];
            float gw, gh, gd;
            float m00, m01, m02, m03;
            gw = B0.y - lf0;  gh = dn0.x - up0.x;  gd = C0.x - A0.x;
            m00 = sqrtf(gw * gw + gh * gh + gd * gd + 1e-6f);
            gw = B0.z - B0.x; gh = dn0.y - up0.y;  gd = C0.y - A0.y;
            m01 = sqrtf(gw * gw + gh * gh + gd * gd + 1e-6f);
            gw = B0.w - B0.y; gh = dn0.z - up0.z;  gd = C0.z - A0.z;
            m02 = sqrtf(gw * gw + gh * gh + gd * gd + 1e-6f);
            gw = rt0 - B0.z;  gh = dn0.w - up0.w;  gd = C0.w - A0.w;
            m03 = sqrtf(gw * gw + gh * gh + gd * gd + 1e-6f);

            // input 1
            float lf1 = (tx > 0)  ? sm[1][ty + 1][w0 - 1] : 0.0f;
            float rt1 = (tx < 63) ? sm[1][ty + 1][w0 + 4] : 0.0f;
            float4 up1 = *(float4*)&sm[1][ty][w0];
            float4 dn1 = *(float4*)&sm[1][ty + 2][w0];
            float m10, m11, m12, m13;
            gw = B1.y - lf1;  gh = dn1.x - up1.x;  gd = C1.x - A1.x;
            m10 = sqrtf(gw * gw + gh * gh + gd * gd + 1e-6f);
            gw = B1.z - B1.x; gh = dn1.y - up1.y;  gd = C1.y - A1.y;
            m11 = sqrtf(gw * gw + gh * gh + gd * gd + 1e-6f);
            gw = B1.w - B1.y; gh = dn1.z - up1.z;  gd = C1.z - A1.z;
            m12 = sqrtf(gw * gw + gh * gh + gd * gd + 1e-6f);
            gw = rt1 - B1.z;  gh = dn1.w - up1.w;  gd = C1.w - A1.w;
            m13 = sqrtf(gw * gw + gh * gh + gd * gd + 1e-6f);

            // edge-pad weights along w (interior w = 1..254)
            float s = 0.0f;
            if (tx > 0)  s += fabsf(m00 - m10);
            s += ((tx == 0)  ? 2.0f : 1.0f) * fabsf(m01 - m11);
            s += ((tx == 63) ? 2.0f : 1.0f) * fabsf(m02 - m12);
            if (tx < 63) s += fabsf(m03 - m13);
            local += wd * wh * s;
        }

        // rotate window
        A0 = B0; A1 = B1; B0 = C0; B1 = C1;
    }

    // ---- block reduction ----
    #pragma unroll
    for (int off = 16; off > 0; off >>= 1)
        local += __shfl_xor_sync(0xffffffffu, local, off);

    const int tid  = ty * 64 + tx;
    const int warp = tid >> 5;
    const int lane = tid & 31;
    if (lane == 0) ssum[warp] = local;
    __syncthreads();

    if (tid == 0) {
        float v = 0.0f;
        #pragma unroll
        for (int i = 0; i < 8; ++i) v += ssum[i];
        g_partials[bid] = v;
        __threadfence();
        unsigned int t = atomicInc(&g_count, NBLOCKS - 1);
        s_last = (t == NBLOCKS - 1);
    }
    __syncthreads();

    // ---- last block finishes the global reduction ----
    if (s_last) {
        __threadfence();
        float s = 0.0f;
        const volatile float* gp = g_partials;
        for (int i = tid; i < NBLOCKS; i += 256)
            s += gp[i];
        #pragma unroll
        for (int off = 16; off > 0; off >>= 1)
            s += __shfl_xor_sync(0xffffffffu, s, off);
        if (lane == 0) ssum[warp] = s;
        __syncthreads();
        if (warp == 0) {
            float v = (lane < 8) ? ssum[lane] : 0.0f;
            #pragma unroll
            for (int off = 4; off > 0; off >>= 1)
                v += __shfl_xor_sync(0xffffffffu, v, off);
            if (lane == 0)
                out[0] = v * (1.0f / (float)NELEM);
        }
    }
}

extern "C" void kernel_launch(void* const* d_in, const int* in_sizes, int n_in,
                              void* d_out, int out_size) {
    const float* x1 = (const float*)d_in[0];
    const float* x2 = (const float*)d_in[1];
    float* out = (float*)d_out;
    (void)in_sizes; (void)n_in; (void)out_size;

    dim3 block(64, 4, 1);
    dim3 grid(HTILES, DCHUNKS, 1);
    grad_loss_fused<<<grid, block>>>(x1, x2, out);
}